// round 3
// baseline (speedup 1.0000x reference)
#include <cuda_runtime.h>

// Problem constants
#define Bsz 128          // batch
#define Tsz 800          // seq len
#define Isz 300          // input dim
#define Hsz 32           // hidden
#define Gsz 128          // 4*H
#define NBH 4096         // B*H
#define NCHUNK 25        // T / 32

// ---------------- scratch (static __device__, no runtime alloc) -------------
__device__ float g_gx[(size_t)Bsz * Tsz * Gsz];    // [B*T, 4H]  52.4 MB
__device__ float g_hsT[(size_t)Tsz * Bsz * Hsz];   // [T, B, H]  13.1 MB (t-major!)
__device__ float g_q2[(size_t)Tsz * NBH];          // [T, B*H]   13.1 MB
__device__ float g_fcpart[Bsz * NCHUNK];           // deterministic partials
__device__ float g_qk_scratch[(size_t)Bsz * Tsz * Hsz];  // fallback if out is fc-only
__device__ float g_fc_scratch[Bsz];                      // fallback if out is qk-only

// ============================================================================
// Kernel 1: gx[b,t,:] = x[b,t,:] @ W_ih^T + (b_ih + b_hh)
// GEMM: M = B*T = 102400, N = 128, K = 300.  BM=128, BN=128, BK=12 (300=25*12).
// 256 threads, 8x8 per thread. Padded smem (132) kills STS bank conflicts.
// ============================================================================
#define BK1 12
__global__ __launch_bounds__(256) void gemm_gx(const float* __restrict__ X,
                                               const float* __restrict__ Wih,
                                               const float* __restrict__ bih,
                                               const float* __restrict__ bhh) {
    __shared__ float As[BK1][132];
    __shared__ float Bs[BK1][132];
    const int m0  = blockIdx.x * 128;
    const int tid = threadIdx.x;
    const int tm  = tid >> 4;       // 0..15
    const int tn  = tid & 15;       // 0..15

    float acc[8][8];
#pragma unroll
    for (int i = 0; i < 8; i++)
#pragma unroll
        for (int j = 0; j < 8; j++) acc[i][j] = 0.f;

    for (int k0 = 0; k0 < Isz; k0 += BK1) {
#pragma unroll
        for (int i = 0; i < 6; i++) {              // 1536 elems / 256 thr
            int idx = tid + i * 256;
            int r = idx / BK1;
            int c = idx - r * BK1;
            As[c][r] = X[(size_t)(m0 + r) * Isz + k0 + c];
            Bs[c][r] = Wih[(size_t)r * Isz + k0 + c];
        }
        __syncthreads();
#pragma unroll
        for (int k = 0; k < BK1; k++) {
            float av[8], bv[8];
            *(float4*)&av[0] = *(const float4*)&As[k][tm * 8];
            *(float4*)&av[4] = *(const float4*)&As[k][tm * 8 + 4];
            *(float4*)&bv[0] = *(const float4*)&Bs[k][tn * 8];
            *(float4*)&bv[4] = *(const float4*)&Bs[k][tn * 8 + 4];
#pragma unroll
            for (int i = 0; i < 8; i++)
#pragma unroll
                for (int j = 0; j < 8; j++)
                    acc[i][j] = fmaf(av[i], bv[j], acc[i][j]);
        }
        __syncthreads();
    }

    float bias[8];
#pragma unroll
    for (int j = 0; j < 8; j++) bias[j] = bih[tn * 8 + j] + bhh[tn * 8 + j];
#pragma unroll
    for (int i = 0; i < 8; i++) {
        size_t row = (size_t)(m0 + tm * 8 + i) * Gsz;
#pragma unroll
        for (int j = 0; j < 8; j++)
            g_gx[row + tn * 8 + j] = acc[i][j] + bias[j];
    }
}

// ============================================================================
// Kernel 2: LSTM recurrence.  1 CTA per batch element, 128 threads = 4H rows.
// Thread j owns W_hh row j in 32 registers; h lives in smem; c in registers of
// warp 0. Warp 2 (j in [64,96)) is exactly the tanh gate -> no divergence.
// Stores h TRANSPOSED: g_hsT[t][b][h]  (feeds GEMM2 with contiguous N).
// ============================================================================
__global__ __launch_bounds__(128) void lstm_scan(const float* __restrict__ Whh) {
    const int b = blockIdx.x;
    const int j = threadIdx.x;
    __shared__ __align__(16) float sh_h[Hsz];
    __shared__ float sh_act[Gsz];

    float w[Hsz];
#pragma unroll
    for (int k = 0; k < Hsz; k++) w[k] = Whh[j * Hsz + k];

    float c = 0.f;
    if (j < Hsz) sh_h[j] = 0.f;
    __syncthreads();

    const float* gxb = g_gx + (size_t)b * Tsz * Gsz;
    float gcur  = gxb[j];
    float gnext = gxb[Gsz + j];

    for (int t = 0; t < Tsz; t++) {
        float gpre = (t + 2 < Tsz) ? gxb[(size_t)(t + 2) * Gsz + j] : 0.f;

        float hv[Hsz];
#pragma unroll
        for (int q = 0; q < Hsz / 4; q++)
            *(float4*)&hv[q * 4] = *(const float4*)&sh_h[q * 4];

        // 4-way split accumulation: shortens the serial FMA chain 4x
        float s0 = gcur, s1 = 0.f, s2 = 0.f, s3 = 0.f;
#pragma unroll
        for (int k = 0; k < Hsz; k += 4) {
            s0 = fmaf(w[k + 0], hv[k + 0], s0);
            s1 = fmaf(w[k + 1], hv[k + 1], s1);
            s2 = fmaf(w[k + 2], hv[k + 2], s2);
            s3 = fmaf(w[k + 3], hv[k + 3], s3);
        }
        float g = (s0 + s1) + (s2 + s3);

        float a;
        if (j >= 64 && j < 96) a = tanhf(g);                 // g gate (warp 2)
        else                   a = 1.0f / (1.0f + __expf(-g)); // i, f, o gates
        sh_act[j] = a;
        __syncthreads();

        if (j < Hsz) {
            c = sh_act[Hsz + j] * c + sh_act[j] * sh_act[2 * Hsz + j];
            float h = sh_act[3 * Hsz + j] * tanhf(c);
            sh_h[j] = h;
            g_hsT[(size_t)t * NBH + b * Hsz + j] = h;
        }
        __syncthreads();

        gcur = gnext;
        gnext = gpre;
    }
}

// ============================================================================
// Kernel 3: q2[s, n] = sum_t Ww[s,t] * hsT[t, n]   (n = b*H + h)
// Single GEMM: M=800, N=4096, K=800.  BM=BN=128, BK=8. B operand contiguous.
// ============================================================================
#define BK2 8
__global__ __launch_bounds__(256) void gemm_q(const float* __restrict__ Ww) {
    __shared__ float As[BK2][132];
    __shared__ __align__(16) float Bs[BK2][128];
    const int m0  = blockIdx.x * 128;
    const int n0  = blockIdx.y * 128;
    const int tid = threadIdx.x;
    const int tm  = tid >> 4;
    const int tn  = tid & 15;

    float acc[8][8];
#pragma unroll
    for (int i = 0; i < 8; i++)
#pragma unroll
        for (int j = 0; j < 8; j++) acc[i][j] = 0.f;

    for (int k0 = 0; k0 < Tsz; k0 += BK2) {
#pragma unroll
        for (int i = 0; i < 4; i++) {               // A: 1024 elems / 256 thr
            int idx = tid + i * 256;
            int r = idx >> 3;
            int c = idx & 7;
            int m = m0 + r;
            As[c][r] = (m < Tsz) ? Ww[(size_t)m * Tsz + k0 + c] : 0.f;
        }
        {                                           // B: 8 x 128, one float4/thr
            int r  = tid >> 5;
            int c4 = tid & 31;
            *(float4*)&Bs[r][c4 * 4] =
                *(const float4*)&g_hsT[(size_t)(k0 + r) * NBH + n0 + c4 * 4];
        }
        __syncthreads();
#pragma unroll
        for (int k = 0; k < BK2; k++) {
            float av[8], bv[8];
            *(float4*)&av[0] = *(const float4*)&As[k][tm * 8];
            *(float4*)&av[4] = *(const float4*)&As[k][tm * 8 + 4];
            *(float4*)&bv[0] = *(const float4*)&Bs[k][tn * 8];
            *(float4*)&bv[4] = *(const float4*)&Bs[k][tn * 8 + 4];
#pragma unroll
            for (int i = 0; i < 8; i++)
#pragma unroll
                for (int j = 0; j < 8; j++)
                    acc[i][j] = fmaf(av[i], bv[j], acc[i][j]);
        }
        __syncthreads();
    }

#pragma unroll
    for (int i = 0; i < 8; i++) {
        int m = m0 + tm * 8 + i;
        if (m < Tsz) {
            size_t row = (size_t)m * NBH + n0 + tn * 8;
#pragma unroll
            for (int j = 0; j < 8; j++) g_q2[row + j] = acc[i][j];
        }
    }
}

// ============================================================================
// Kernel 4: qk[b,t,h] = hsT[t,b,h] * (q2[t,b,h] + bw[t]); partial fc dot per
// (b, t-chunk) written deterministically to g_fcpart.
// ============================================================================
__global__ __launch_bounds__(256) void qk_fc_kernel(const float* __restrict__ bw,
                                                    const float* __restrict__ Wfc,
                                                    float* __restrict__ qk_out) {
    const int b   = blockIdx.x;
    const int ch  = blockIdx.y;         // 0..24, each covers 32 t's
    const int tid = threadIdx.x;
    const int h   = tid & 31;
    const int tl  = tid >> 5;           // 8 t lanes per pass

    float partial = 0.f;
#pragma unroll
    for (int tt = 0; tt < 32; tt += 8) {
        int t = ch * 32 + tt + tl;
        size_t idxT = (size_t)t * NBH + b * Hsz + h;
        float o  = g_hsT[idxT];
        float qv = g_q2[idxT] + bw[t];
        float v  = o * qv;
        qk_out[(size_t)b * (Tsz * Hsz) + (size_t)t * Hsz + h] = v;
        partial = fmaf(v, Wfc[t * Hsz + h], partial);
    }

    __shared__ float red[256];
    red[tid] = partial;
    __syncthreads();
#pragma unroll
    for (int s = 128; s > 0; s >>= 1) {
        if (tid < s) red[tid] += red[tid + s];
        __syncthreads();
    }
    if (tid == 0) g_fcpart[b * NCHUNK + ch] = red[0];
}

// Kernel 5: out_fc[b] = sum(partials) + bfc
__global__ void fc_final(const float* __restrict__ bfc, float* __restrict__ fc_out) {
    int b = threadIdx.x;
    float s = bfc[0];
#pragma unroll
    for (int i = 0; i < NCHUNK; i++) s += g_fcpart[b * NCHUNK + i];
    fc_out[b] = s;
}

// ============================================================================
// Launcher
// ============================================================================
extern "C" void kernel_launch(void* const* d_in, const int* in_sizes, int n_in,
                              void* d_out, int out_size) {
    const float* x   = (const float*)d_in[0];
    const float* Wih = (const float*)d_in[1];
    const float* Whh = (const float*)d_in[2];
    const float* bih = (const float*)d_in[3];
    const float* bhh = (const float*)d_in[4];
    const float* Ww  = (const float*)d_in[5];
    const float* bw  = (const float*)d_in[6];
    const float* Wfc = (const float*)d_in[7];
    const float* bfc = (const float*)d_in[8];
    float* out = (float*)d_out;

    const long QK = (long)Bsz * Tsz * Hsz;   // 3,276,800
    float* fc_out;
    float* qk_out;
    if (out_size == (int)(QK + Bsz)) {       // tuple (out_fc, qk) concatenated
        fc_out = out;
        qk_out = out + Bsz;
    } else if (out_size == (int)QK) {        // qk only
        qk_out = out;
        cudaGetSymbolAddress((void**)&fc_out, g_fc_scratch);
    } else {                                 // fc only (or unknown -> fc first)
        fc_out = out;
        cudaGetSymbolAddress((void**)&qk_out, g_qk_scratch);
    }

    // 1. input projection GEMM (102400 x 128 x 300)
    gemm_gx<<<(Bsz * Tsz) / 128, 256>>>(x, Wih, bih, bhh);

    // 2. sequential LSTM scan (1 CTA / batch element)
    lstm_scan<<<Bsz, 128>>>(Whh);

    // 3. attention GEMM (800 x 4096 x 800)
    dim3 g2((Tsz + 127) / 128, NBH / 128);   // (7, 32)
    gemm_q<<<g2, 256>>>(Ww);

    // 4. elementwise qk + fc partials
    dim3 g3(Bsz, NCHUNK);
    qk_fc_kernel<<<g3, 256>>>(bw, Wfc, qk_out);

    // 5. final fc reduction
    fc_final<<<1, Bsz>>>(bfc, fc_out);
}

// round 4
// speedup vs baseline: 1.4328x; 1.4328x over previous
#include <cuda_runtime.h>
#include <cuda_bf16.h>
#include <cstdint>

// Problem constants
#define Bsz 128          // batch
#define Tsz 800          // seq len
#define Isz 300          // input dim
#define Hsz 32           // hidden
#define Gsz 128          // 4*H
#define NBH 4096         // B*H
#define NCHUNK 25        // T / 32

// ---------------- scratch (static __device__, no runtime alloc) -------------
__device__ float g_gx[(size_t)Bsz * Tsz * Gsz];    // [B*T, 4H]  52.4 MB
__device__ float g_hsT[(size_t)Tsz * NBH];         // [T, B*H]   13.1 MB (t-major)
__device__ float g_fcpart[Bsz * NCHUNK];           // deterministic partials
__device__ float g_qk_scratch[(size_t)Bsz * Tsz * Hsz];
__device__ float g_fc_scratch[Bsz];

// ---------------- PTX helpers ----------------------------------------------
__device__ __forceinline__ uint32_t sptr(const void* p) {
    return (uint32_t)__cvta_generic_to_shared(p);
}
__device__ __forceinline__ void ldsm4(uint32_t* r, uint32_t a) {
    asm volatile("ldmatrix.sync.aligned.m8n8.x4.shared.b16 {%0,%1,%2,%3}, [%4];"
                 : "=r"(r[0]), "=r"(r[1]), "=r"(r[2]), "=r"(r[3]) : "r"(a));
}
__device__ __forceinline__ void ldsm4t(uint32_t* r, uint32_t a) {
    asm volatile("ldmatrix.sync.aligned.m8n8.x4.trans.shared.b16 {%0,%1,%2,%3}, [%4];"
                 : "=r"(r[0]), "=r"(r[1]), "=r"(r[2]), "=r"(r[3]) : "r"(a));
}
__device__ __forceinline__ void mma16816(float* d, const uint32_t* a, const uint32_t* b) {
    asm volatile(
        "mma.sync.aligned.m16n8k16.row.col.f32.bf16.bf16.f32 "
        "{%0,%1,%2,%3}, {%4,%5,%6,%7}, {%8,%9}, {%0,%1,%2,%3};"
        : "+f"(d[0]), "+f"(d[1]), "+f"(d[2]), "+f"(d[3])
        : "r"(a[0]), "r"(a[1]), "r"(a[2]), "r"(a[3]), "r"(b[0]), "r"(b[1]));
}

// Split 8 fp32 into bf16 hi/lo and store as one uint4 each (16B STS).
__device__ __forceinline__ void cvt_store8(__nv_bfloat16* dhi, __nv_bfloat16* dlo,
                                           const float* v) {
    uint32_t hi[4], lo[4];
#pragma unroll
    for (int i = 0; i < 4; i++) {
        __nv_bfloat16 h0 = __float2bfloat16(v[2 * i]);
        __nv_bfloat16 h1 = __float2bfloat16(v[2 * i + 1]);
        __nv_bfloat16 l0 = __float2bfloat16(v[2 * i]     - __bfloat162float(h0));
        __nv_bfloat16 l1 = __float2bfloat16(v[2 * i + 1] - __bfloat162float(h1));
        __nv_bfloat162 hh = __halves2bfloat162(h0, h1);
        __nv_bfloat162 ll = __halves2bfloat162(l0, l1);
        hi[i] = *reinterpret_cast<uint32_t*>(&hh);
        lo[i] = *reinterpret_cast<uint32_t*>(&ll);
    }
    *reinterpret_cast<uint4*>(dhi) = make_uint4(hi[0], hi[1], hi[2], hi[3]);
    *reinterpret_cast<uint4*>(dlo) = make_uint4(lo[0], lo[1], lo[2], lo[3]);
}

// ============================================================================
// Kernel 1: gx = x @ W_ih^T + (b_ih + b_hh), split-bf16 tensor cores.
// M=102400, N=128, K=300 (pad 304). BM=128, BN=128, 8 warps (4m x 2n),
// warp tile 32x64, mma m16n8k16. Smem [row][k] pitch 24 bf16 (conflict-free
// ldmatrix). 3 mma passes per k16: AhiBhi + AloBhi + AhiBlo.
// ============================================================================
#define APAD 24
__global__ __launch_bounds__(256, 2) void gemm_gx_mma(
    const float* __restrict__ X, const float* __restrict__ Wih,
    const float* __restrict__ bih, const float* __restrict__ bhh) {
    __shared__ __align__(16) __nv_bfloat16 sAhi[128 * APAD], sAlo[128 * APAD];
    __shared__ __align__(16) __nv_bfloat16 sBhi[128 * APAD], sBlo[128 * APAD];

    const int m0   = blockIdx.x * 128;
    const int tid  = threadIdx.x;
    const int lane = tid & 31;
    const int wid  = tid >> 5;
    const int wm   = wid >> 1;      // 0..3
    const int wn   = wid & 1;       // 0..1

    float acc[2][8][4];
#pragma unroll
    for (int mi = 0; mi < 2; mi++)
#pragma unroll
        for (int ni = 0; ni < 8; ni++)
#pragma unroll
            for (int e = 0; e < 4; e++) acc[mi][ni][e] = 0.f;

    // load assignment: 2 threads per row, 8 k each
    const int lr = tid >> 1;
    const int lk = (tid & 1) * 8;

    // ldmatrix addresses (constant across k-loop)
    const int amrow = lane & 15;
    const int akcol = (lane >> 4) * 8;
    uint32_t aAhi[2], aAlo[2];
#pragma unroll
    for (int mi = 0; mi < 2; mi++) {
        int r = wm * 32 + mi * 16 + amrow;
        aAhi[mi] = sptr(&sAhi[r * APAD + akcol]);
        aAlo[mi] = sptr(&sAlo[r * APAD + akcol]);
    }
    const int bnrow = (lane & 7) + ((lane & 16) >> 1);   // 0..15
    const int bkcol = (lane & 8) ? 8 : 0;
    uint32_t aBhi[4], aBlo[4];
#pragma unroll
    for (int nb = 0; nb < 4; nb++) {
        int r = wn * 64 + nb * 16 + bnrow;
        aBhi[nb] = sptr(&sBhi[r * APAD + bkcol]);
        aBlo[nb] = sptr(&sBlo[r * APAD + bkcol]);
    }

#pragma unroll 1
    for (int k0 = 0; k0 < 304; k0 += 16) {
        // ---- load + split-convert A (x) and B (W_ih) tiles ----
        float va[8], vb[8];
        if (k0 + lk + 7 < Isz) {
            *(float4*)&va[0] = *(const float4*)&X[(size_t)(m0 + lr) * Isz + k0 + lk];
            *(float4*)&va[4] = *(const float4*)&X[(size_t)(m0 + lr) * Isz + k0 + lk + 4];
            *(float4*)&vb[0] = *(const float4*)&Wih[(size_t)lr * Isz + k0 + lk];
            *(float4*)&vb[4] = *(const float4*)&Wih[(size_t)lr * Isz + k0 + lk + 4];
        } else {
#pragma unroll
            for (int j = 0; j < 8; j++) {
                int k = k0 + lk + j;
                va[j] = (k < Isz) ? X[(size_t)(m0 + lr) * Isz + k] : 0.f;
                vb[j] = (k < Isz) ? Wih[(size_t)lr * Isz + k] : 0.f;
            }
        }
        cvt_store8(&sAhi[lr * APAD + lk], &sAlo[lr * APAD + lk], va);
        cvt_store8(&sBhi[lr * APAD + lk], &sBlo[lr * APAD + lk], vb);
        __syncthreads();

        // ---- fragments + 3 mma passes ----
        uint32_t afr[2][4], alo[2][4], bfr[8][2];
        ldsm4(afr[0], aAhi[0]);
        ldsm4(afr[1], aAhi[1]);
#pragma unroll
        for (int nb = 0; nb < 4; nb++) {
            uint32_t r[4];
            ldsm4(r, aBhi[nb]);
            bfr[2 * nb][0] = r[0]; bfr[2 * nb][1] = r[1];
            bfr[2 * nb + 1][0] = r[2]; bfr[2 * nb + 1][1] = r[3];
        }
#pragma unroll
        for (int mi = 0; mi < 2; mi++)
#pragma unroll
            for (int ni = 0; ni < 8; ni++) mma16816(acc[mi][ni], afr[mi], bfr[ni]);

        ldsm4(alo[0], aAlo[0]);
        ldsm4(alo[1], aAlo[1]);
#pragma unroll
        for (int mi = 0; mi < 2; mi++)
#pragma unroll
            for (int ni = 0; ni < 8; ni++) mma16816(acc[mi][ni], alo[mi], bfr[ni]);

#pragma unroll
        for (int nb = 0; nb < 4; nb++) {
            uint32_t r[4];
            ldsm4(r, aBlo[nb]);
            bfr[2 * nb][0] = r[0]; bfr[2 * nb][1] = r[1];
            bfr[2 * nb + 1][0] = r[2]; bfr[2 * nb + 1][1] = r[3];
        }
#pragma unroll
        for (int mi = 0; mi < 2; mi++)
#pragma unroll
            for (int ni = 0; ni < 8; ni++) mma16816(acc[mi][ni], afr[mi], bfr[ni]);
        __syncthreads();
    }

    // ---- epilogue: add bias, store ----
    const int er = lane >> 2;
    const int ec = (lane & 3) * 2;
    float bias0[8], bias1[8];
#pragma unroll
    for (int ni = 0; ni < 8; ni++) {
        int col = wn * 64 + ni * 8 + ec;
        bias0[ni] = bih[col] + bhh[col];
        bias1[ni] = bih[col + 1] + bhh[col + 1];
    }
#pragma unroll
    for (int mi = 0; mi < 2; mi++) {
        int row = m0 + wm * 32 + mi * 16 + er;
#pragma unroll
        for (int ni = 0; ni < 8; ni++) {
            int col = wn * 64 + ni * 8 + ec;
            float2 v0 = make_float2(acc[mi][ni][0] + bias0[ni], acc[mi][ni][1] + bias1[ni]);
            float2 v1 = make_float2(acc[mi][ni][2] + bias0[ni], acc[mi][ni][3] + bias1[ni]);
            *(float2*)&g_gx[(size_t)row * Gsz + col]       = v0;
            *(float2*)&g_gx[(size_t)(row + 8) * Gsz + col] = v1;
        }
    }
}

// ============================================================================
// Kernel 2: LSTM recurrence. 1 CTA / batch element, 128 threads = 4H rows.
// Row j = gate (j>>5), unit (j&31). All 4 warps redundantly track (c,h) for
// unit=lane; h exchanged via __shfl (no smem); activations exchanged through a
// double-buffered smem tile -> ONE barrier per step.
// ============================================================================
__global__ __launch_bounds__(128) void lstm_scan(const float* __restrict__ Whh) {
    const int b    = blockIdx.x;
    const int j    = threadIdx.x;
    const int lane = j & 31;
    const int wid  = j >> 5;
    __shared__ __align__(16) float sh_act[2][Gsz];   // [buf][unit*4 + gate]

    float w[Hsz];
#pragma unroll
    for (int k = 0; k < Hsz; k++) w[k] = Whh[j * Hsz + k];

    float c = 0.f, h = 0.f;
    const float* gxb = g_gx + (size_t)b * Tsz * Gsz;
    float gcur  = gxb[j];
    float gnext = gxb[Gsz + j];
    const bool is_g = (wid == 2);

    for (int t = 0; t < Tsz; t++) {
        float gpre = (t + 2 < Tsz) ? gxb[(size_t)(t + 2) * Gsz + j] : 0.f;

        // z = gx + W_hh[j,:] . h   (h broadcast via shfl, 4-way split chains)
        float s0 = gcur, s1 = 0.f, s2 = 0.f, s3 = 0.f;
#pragma unroll
        for (int k = 0; k < Hsz; k += 4) {
            s0 = fmaf(w[k],     __shfl_sync(0xffffffffu, h, k),     s0);
            s1 = fmaf(w[k + 1], __shfl_sync(0xffffffffu, h, k + 1), s1);
            s2 = fmaf(w[k + 2], __shfl_sync(0xffffffffu, h, k + 2), s2);
            s3 = fmaf(w[k + 3], __shfl_sync(0xffffffffu, h, k + 3), s3);
        }
        float z = (s0 + s1) + (s2 + s3);

        float a;
        if (is_g) a = 2.f / (1.f + __expf(-2.f * z)) - 1.f;   // tanh
        else      a = 1.f / (1.f + __expf(-z));               // sigmoid
        sh_act[t & 1][lane * 4 + wid] = a;
        __syncthreads();

        float4 g4 = *(const float4*)&sh_act[t & 1][lane * 4];  // (i,f,g,o)
        c = fmaf(g4.y, c, g4.x * g4.z);
        float tc = 2.f / (1.f + __expf(-2.f * c)) - 1.f;
        h = g4.w * tc;
        if (wid == 0) g_hsT[(size_t)t * NBH + b * Hsz + lane] = h;

        gcur = gnext;
        gnext = gpre;
    }
}

// ============================================================================
// Kernel 3: q[s,n] = sum_t Ww[s,t] * hsT[t,n], split-bf16 tensor cores, with
// FUSED qk epilogue:  qk[b,s,h] = hsT[s,n] * (q + bw[s]),  n = b*32 + h.
// M=800, N=4096, K=800. A smem [m][k] pitch 24; B smem [k][n] pitch 136
// loaded via ldmatrix.trans (conflict-free: 272B row stride).
// ============================================================================
#define BPAD 136
__global__ __launch_bounds__(256, 2) void gemm_q_mma(
    const float* __restrict__ Ww, const float* __restrict__ bw,
    float* __restrict__ qk_out) {
    __shared__ __align__(16) __nv_bfloat16 sAhi[128 * APAD], sAlo[128 * APAD];
    __shared__ __align__(16) __nv_bfloat16 sBhi[16 * BPAD],  sBlo[16 * BPAD];

    const int m0   = blockIdx.x * 128;
    const int n0   = blockIdx.y * 128;
    const int tid  = threadIdx.x;
    const int lane = tid & 31;
    const int wid  = tid >> 5;
    const int wm   = wid >> 1;
    const int wn   = wid & 1;

    float acc[2][8][4];
#pragma unroll
    for (int mi = 0; mi < 2; mi++)
#pragma unroll
        for (int ni = 0; ni < 8; ni++)
#pragma unroll
            for (int e = 0; e < 4; e++) acc[mi][ni][e] = 0.f;

    const int alr = tid >> 1;        // A row (m), 8 k each
    const int alk = (tid & 1) * 8;
    const int blr = tid >> 4;        // B row (k), 8 n each
    const int bln = (tid & 15) * 8;

    const int amrow = lane & 15;
    const int akcol = (lane >> 4) * 8;
    uint32_t aAhi[2], aAlo[2];
#pragma unroll
    for (int mi = 0; mi < 2; mi++) {
        int r = wm * 32 + mi * 16 + amrow;
        aAhi[mi] = sptr(&sAhi[r * APAD + akcol]);
        aAlo[mi] = sptr(&sAlo[r * APAD + akcol]);
    }
    const int qbrow = lane & 15;          // k row
    const int qbcol = (lane >> 4) * 8;    // n offset within 16-block
    uint32_t aBhi[4], aBlo[4];
#pragma unroll
    for (int nb = 0; nb < 4; nb++) {
        int coff = wn * 64 + nb * 16 + qbcol;
        aBhi[nb] = sptr(&sBhi[qbrow * BPAD + coff]);
        aBlo[nb] = sptr(&sBlo[qbrow * BPAD + coff]);
    }

#pragma unroll 1
    for (int k0 = 0; k0 < Tsz; k0 += 16) {
        // ---- A tile (Ww), guard m ----
        float va[8];
        if (m0 + alr < Tsz) {
            *(float4*)&va[0] = *(const float4*)&Ww[(size_t)(m0 + alr) * Tsz + k0 + alk];
            *(float4*)&va[4] = *(const float4*)&Ww[(size_t)(m0 + alr) * Tsz + k0 + alk + 4];
        } else {
#pragma unroll
            for (int q = 0; q < 8; q++) va[q] = 0.f;
        }
        cvt_store8(&sAhi[alr * APAD + alk], &sAlo[alr * APAD + alk], va);

        // ---- B tile (hsT), always in range ----
        float vb[8];
        *(float4*)&vb[0] = *(const float4*)&g_hsT[(size_t)(k0 + blr) * NBH + n0 + bln];
        *(float4*)&vb[4] = *(const float4*)&g_hsT[(size_t)(k0 + blr) * NBH + n0 + bln + 4];
        cvt_store8(&sBhi[blr * BPAD + bln], &sBlo[blr * BPAD + bln], vb);
        __syncthreads();

        uint32_t afr[2][4], alo2[2][4], bfr[8][2];
        ldsm4(afr[0], aAhi[0]);
        ldsm4(afr[1], aAhi[1]);
#pragma unroll
        for (int nb = 0; nb < 4; nb++) {
            uint32_t r[4];
            ldsm4t(r, aBhi[nb]);
            bfr[2 * nb][0] = r[0]; bfr[2 * nb][1] = r[1];
            bfr[2 * nb + 1][0] = r[2]; bfr[2 * nb + 1][1] = r[3];
        }
#pragma unroll
        for (int mi = 0; mi < 2; mi++)
#pragma unroll
            for (int ni = 0; ni < 8; ni++) mma16816(acc[mi][ni], afr[mi], bfr[ni]);

        ldsm4(alo2[0], aAlo[0]);
        ldsm4(alo2[1], aAlo[1]);
#pragma unroll
        for (int mi = 0; mi < 2; mi++)
#pragma unroll
            for (int ni = 0; ni < 8; ni++) mma16816(acc[mi][ni], alo2[mi], bfr[ni]);

#pragma unroll
        for (int nb = 0; nb < 4; nb++) {
            uint32_t r[4];
            ldsm4t(r, aBlo[nb]);
            bfr[2 * nb][0] = r[0]; bfr[2 * nb][1] = r[1];
            bfr[2 * nb + 1][0] = r[2]; bfr[2 * nb + 1][1] = r[3];
        }
#pragma unroll
        for (int mi = 0; mi < 2; mi++)
#pragma unroll
            for (int ni = 0; ni < 8; ni++) mma16816(acc[mi][ni], afr[mi], bfr[ni]);
        __syncthreads();
    }

    // ---- fused epilogue: qk = hsT * (q + bw) ----
    const int er = lane >> 2;
    const int ec = (lane & 3) * 2;
#pragma unroll
    for (int mi = 0; mi < 2; mi++) {
        int r0 = m0 + wm * 32 + mi * 16 + er;
        int r1 = r0 + 8;
        float bw0 = (r0 < Tsz) ? bw[r0] : 0.f;
        float bw1 = (r1 < Tsz) ? bw[r1] : 0.f;
#pragma unroll
        for (int ni = 0; ni < 8; ni++) {
            int n  = n0 + wn * 64 + ni * 8 + ec;    // n = b*32 + h, even
            int bb = n >> 5, hh = n & 31;
            if (r0 < Tsz) {
                float2 o = *(const float2*)&g_hsT[(size_t)r0 * NBH + n];
                float2 v = make_float2(o.x * (acc[mi][ni][0] + bw0),
                                       o.y * (acc[mi][ni][1] + bw0));
                *(float2*)&qk_out[(size_t)bb * (Tsz * Hsz) + r0 * Hsz + hh] = v;
            }
            if (r1 < Tsz) {
                float2 o = *(const float2*)&g_hsT[(size_t)r1 * NBH + n];
                float2 v = make_float2(o.x * (acc[mi][ni][2] + bw1),
                                       o.y * (acc[mi][ni][3] + bw1));
                *(float2*)&qk_out[(size_t)bb * (Tsz * Hsz) + r1 * Hsz + hh] = v;
            }
        }
    }
}

// ============================================================================
// Kernel 4: deterministic fc partials over qk:  sum_{t,h} qk[b,t,h]*Wfc[t,h]
// ============================================================================
__global__ __launch_bounds__(256) void fc_part(const float* __restrict__ Wfc,
                                               const float* __restrict__ qk) {
    const int b   = blockIdx.x;
    const int ch  = blockIdx.y;
    const int tid = threadIdx.x;
    const int h   = tid & 31;
    const int tl  = tid >> 5;

    float p = 0.f;
#pragma unroll
    for (int tt = 0; tt < 32; tt += 8) {
        int t = ch * 32 + tt + tl;
        p = fmaf(qk[(size_t)b * (Tsz * Hsz) + t * Hsz + h], Wfc[t * Hsz + h], p);
    }
    __shared__ float red[256];
    red[tid] = p;
    __syncthreads();
#pragma unroll
    for (int s = 128; s > 0; s >>= 1) {
        if (tid < s) red[tid] += red[tid + s];
        __syncthreads();
    }
    if (tid == 0) g_fcpart[b * NCHUNK + ch] = red[0];
}

__global__ void fc_final(const float* __restrict__ bfc, float* __restrict__ fc_out) {
    int b = threadIdx.x;
    float s = bfc[0];
#pragma unroll
    for (int i = 0; i < NCHUNK; i++) s += g_fcpart[b * NCHUNK + i];
    fc_out[b] = s;
}

// ============================================================================
// Launcher
// ============================================================================
extern "C" void kernel_launch(void* const* d_in, const int* in_sizes, int n_in,
                              void* d_out, int out_size) {
    const float* x   = (const float*)d_in[0];
    const float* Wih = (const float*)d_in[1];
    const float* Whh = (const float*)d_in[2];
    const float* bih = (const float*)d_in[3];
    const float* bhh = (const float*)d_in[4];
    const float* Ww  = (const float*)d_in[5];
    const float* bw  = (const float*)d_in[6];
    const float* Wfc = (const float*)d_in[7];
    const float* bfc = (const float*)d_in[8];
    float* out = (float*)d_out;

    const long QK = (long)Bsz * Tsz * Hsz;   // 3,276,800
    float* fc_out;
    float* qk_out;
    if (out_size == (int)(QK + Bsz)) {       // tuple (out_fc, qk) concatenated
        fc_out = out;
        qk_out = out + Bsz;
    } else if (out_size == (int)QK) {        // qk only
        qk_out = out;
        cudaGetSymbolAddress((void**)&fc_out, g_fc_scratch);
    } else {                                 // fc only
        fc_out = out;
        cudaGetSymbolAddress((void**)&qk_out, g_qk_scratch);
    }

    // 1. input projection GEMM (split-bf16 tensor cores)
    gemm_gx_mma<<<(Bsz * Tsz) / 128, 256>>>(x, Wih, bih, bhh);

    // 2. sequential LSTM scan
    lstm_scan<<<Bsz, 128>>>(Whh);

    // 3. attention GEMM + fused qk epilogue
    dim3 g2((Tsz + 127) / 128, NBH / 128);   // (7, 32)
    gemm_q_mma<<<g2, 256>>>(Ww, bw, qk_out);

    // 4. fc partials + final
    dim3 g3(Bsz, NCHUNK);
    fc_part<<<g3, 256>>>(Wfc, qk_out);
    fc_final<<<1, Bsz>>>(bfc, fc_out);
}

// round 5
// speedup vs baseline: 1.5325x; 1.0696x over previous
#include <cuda_runtime.h>
#include <cuda_bf16.h>
#include <cstdint>

// Problem constants
#define Bsz 128          // batch
#define Tsz 800          // seq len
#define Isz 300          // input dim
#define IszP 304         // padded to 16
#define Hsz 32           // hidden
#define Gsz 128          // 4*H
#define NBH 4096         // B*H
#define NMB 7            // m-blocks in gemm_q (ceil(800/128))

// ---------------- scratch (static __device__, no runtime alloc) -------------
__device__ float g_gx[(size_t)Bsz * Tsz * Gsz];       // [B*T, 4H]  52.4 MB
__device__ float g_hsT[(size_t)Tsz * NBH];            // [T, B*H] fp32
__device__ __nv_bfloat16 g_hsT_hi[(size_t)Tsz * NBH]; // [T, B*H] bf16 hi
__device__ __nv_bfloat16 g_hsT_lo[(size_t)Tsz * NBH]; // [T, B*H] bf16 lo
__device__ __nv_bfloat16 g_Wih_hi[128 * IszP], g_Wih_lo[128 * IszP];
__device__ __nv_bfloat16 g_Ww_hi[800 * 800],  g_Ww_lo[800 * 800];
__device__ float g_fcpart[Bsz * NMB];                 // deterministic partials
__device__ float g_qk_scratch[(size_t)Bsz * Tsz * Hsz];
__device__ float g_fc_scratch[Bsz];

// ---------------- PTX helpers ----------------------------------------------
__device__ __forceinline__ uint32_t sptr(const void* p) {
    return (uint32_t)__cvta_generic_to_shared(p);
}
__device__ __forceinline__ void ldsm4(uint32_t* r, uint32_t a) {
    asm volatile("ldmatrix.sync.aligned.m8n8.x4.shared.b16 {%0,%1,%2,%3}, [%4];"
                 : "=r"(r[0]), "=r"(r[1]), "=r"(r[2]), "=r"(r[3]) : "r"(a));
}
__device__ __forceinline__ void ldsm4t(uint32_t* r, uint32_t a) {
    asm volatile("ldmatrix.sync.aligned.m8n8.x4.trans.shared.b16 {%0,%1,%2,%3}, [%4];"
                 : "=r"(r[0]), "=r"(r[1]), "=r"(r[2]), "=r"(r[3]) : "r"(a));
}
__device__ __forceinline__ void mma16816(float* d, const uint32_t* a, const uint32_t* b) {
    asm volatile(
        "mma.sync.aligned.m16n8k16.row.col.f32.bf16.bf16.f32 "
        "{%0,%1,%2,%3}, {%4,%5,%6,%7}, {%8,%9}, {%0,%1,%2,%3};"
        : "+f"(d[0]), "+f"(d[1]), "+f"(d[2]), "+f"(d[3])
        : "r"(a[0]), "r"(a[1]), "r"(a[2]), "r"(a[3]), "r"(b[0]), "r"(b[1]));
}

// Split 8 fp32 -> bf16 hi/lo, one uint4 STS each.
__device__ __forceinline__ void cvt_store8(__nv_bfloat16* dhi, __nv_bfloat16* dlo,
                                           const float* v) {
    uint32_t hi[4], lo[4];
#pragma unroll
    for (int i = 0; i < 4; i++) {
        __nv_bfloat16 h0 = __float2bfloat16(v[2 * i]);
        __nv_bfloat16 h1 = __float2bfloat16(v[2 * i + 1]);
        __nv_bfloat16 l0 = __float2bfloat16(v[2 * i]     - __bfloat162float(h0));
        __nv_bfloat16 l1 = __float2bfloat16(v[2 * i + 1] - __bfloat162float(h1));
        __nv_bfloat162 hh = __halves2bfloat162(h0, h1);
        __nv_bfloat162 ll = __halves2bfloat162(l0, l1);
        hi[i] = *reinterpret_cast<uint32_t*>(&hh);
        lo[i] = *reinterpret_cast<uint32_t*>(&ll);
    }
    *reinterpret_cast<uint4*>(dhi) = make_uint4(hi[0], hi[1], hi[2], hi[3]);
    *reinterpret_cast<uint4*>(dlo) = make_uint4(lo[0], lo[1], lo[2], lo[3]);
}

// ---------------- prep: one-time fp32 -> bf16 hi/lo splits ------------------
__global__ __launch_bounds__(256) void cvt_wih(const float* __restrict__ W) {
    int i = blockIdx.x * 256 + threadIdx.x;
    if (i >= 128 * IszP) return;
    int r = i / IszP, c = i - r * IszP;
    float v = (c < Isz) ? W[r * Isz + c] : 0.f;
    __nv_bfloat16 h = __float2bfloat16(v);
    g_Wih_hi[i] = h;
    g_Wih_lo[i] = __float2bfloat16(v - __bfloat162float(h));
}
__global__ __launch_bounds__(256) void cvt_ww(const float* __restrict__ W) {
    int i = blockIdx.x * 256 + threadIdx.x;
    if (i >= 800 * 800) return;
    float v = W[i];
    __nv_bfloat16 h = __float2bfloat16(v);
    g_Ww_hi[i] = h;
    g_Ww_lo[i] = __float2bfloat16(v - __bfloat162float(h));
}

// ============================================================================
// Kernel 1: gx = x @ W_ih^T + (b_ih + b_hh), split-bf16 HMMA, pipelined.
// M=102400, N=128, K=304. BM=BN=128, 8 warps (4m x 2n), warp tile 32x64.
// Double-buffered smem + register prefetch; ONE bar per k-iter.
// A (x) converted in-kernel; B (W_ih) pre-converted bf16 hi/lo.
// ============================================================================
#define APAD 24
#define NIT1 (IszP / 16)     // 19
__global__ __launch_bounds__(256, 2) void gemm_gx_mma(
    const float* __restrict__ X,
    const float* __restrict__ bih, const float* __restrict__ bhh) {
    __shared__ __align__(16) __nv_bfloat16 sAhi[2][128 * APAD], sAlo[2][128 * APAD];
    __shared__ __align__(16) __nv_bfloat16 sBhi[2][128 * APAD], sBlo[2][128 * APAD];

    const int m0   = blockIdx.x * 128;
    const int tid  = threadIdx.x;
    const int lane = tid & 31;
    const int wid  = tid >> 5;
    const int wm   = wid >> 1;
    const int wn   = wid & 1;

    float acc[2][8][4];
#pragma unroll
    for (int mi = 0; mi < 2; mi++)
#pragma unroll
        for (int ni = 0; ni < 8; ni++)
#pragma unroll
            for (int e = 0; e < 4; e++) acc[mi][ni][e] = 0.f;

    const int lr = tid >> 1;          // row, 2 threads per row
    const int lk = (tid & 1) * 8;     // 8 k each

    // ldmatrix base offsets (element units), add buffer base at use
    const int amrow = lane & 15;
    const int akcol = (lane >> 4) * 8;
    int offA[2];
#pragma unroll
    for (int mi = 0; mi < 2; mi++)
        offA[mi] = (wm * 32 + mi * 16 + amrow) * APAD + akcol;
    const int bnrow = (lane & 7) + ((lane & 16) >> 1);
    const int bkcol = (lane & 8) ? 8 : 0;
    int offB[4];
#pragma unroll
    for (int nb = 0; nb < 4; nb++)
        offB[nb] = (wn * 64 + nb * 16 + bnrow) * APAD + bkcol;

    // prefetch registers
    float va[8];
    uint4 pbh, pbl;

    auto loadA = [&](int k0) {
        if (k0 + lk + 7 < Isz) {
            *(float4*)&va[0] = *(const float4*)&X[(size_t)(m0 + lr) * Isz + k0 + lk];
            *(float4*)&va[4] = *(const float4*)&X[(size_t)(m0 + lr) * Isz + k0 + lk + 4];
        } else {
#pragma unroll
            for (int j = 0; j < 8; j++) {
                int k = k0 + lk + j;
                va[j] = (k < Isz) ? X[(size_t)(m0 + lr) * Isz + k] : 0.f;
            }
        }
    };
    auto loadB = [&](int k0) {
        pbh = *(const uint4*)&g_Wih_hi[lr * IszP + k0 + lk];
        pbl = *(const uint4*)&g_Wih_lo[lr * IszP + k0 + lk];
    };
    auto stA = [&](int buf) {
        cvt_store8(&sAhi[buf][lr * APAD + lk], &sAlo[buf][lr * APAD + lk], va);
    };
    auto stB = [&](int buf) {
        *(uint4*)&sBhi[buf][lr * APAD + lk] = pbh;
        *(uint4*)&sBlo[buf][lr * APAD + lk] = pbl;
    };

    loadA(0); loadB(0);
    stA(0); stB(0);
    __syncthreads();

#pragma unroll 1
    for (int it = 0; it < NIT1; it++) {
        const int cur = it & 1;
        const bool more = (it + 1 < NIT1);
        if (more) { loadA((it + 1) * 16); loadB((it + 1) * 16); }

        uint32_t afr[2][4], alo[2][4], bfr[8][2];
        ldsm4(afr[0], sptr(&sAhi[cur][offA[0]]));
        ldsm4(afr[1], sptr(&sAhi[cur][offA[1]]));
#pragma unroll
        for (int nb = 0; nb < 4; nb++) {
            uint32_t r[4];
            ldsm4(r, sptr(&sBhi[cur][offB[nb]]));
            bfr[2 * nb][0] = r[0]; bfr[2 * nb][1] = r[1];
            bfr[2 * nb + 1][0] = r[2]; bfr[2 * nb + 1][1] = r[3];
        }
#pragma unroll
        for (int mi = 0; mi < 2; mi++)
#pragma unroll
            for (int ni = 0; ni < 8; ni++) mma16816(acc[mi][ni], afr[mi], bfr[ni]);

        ldsm4(alo[0], sptr(&sAlo[cur][offA[0]]));
        ldsm4(alo[1], sptr(&sAlo[cur][offA[1]]));
#pragma unroll
        for (int mi = 0; mi < 2; mi++)
#pragma unroll
            for (int ni = 0; ni < 8; ni++) mma16816(acc[mi][ni], alo[mi], bfr[ni]);

#pragma unroll
        for (int nb = 0; nb < 4; nb++) {
            uint32_t r[4];
            ldsm4(r, sptr(&sBlo[cur][offB[nb]]));
            bfr[2 * nb][0] = r[0]; bfr[2 * nb][1] = r[1];
            bfr[2 * nb + 1][0] = r[2]; bfr[2 * nb + 1][1] = r[3];
        }
#pragma unroll
        for (int mi = 0; mi < 2; mi++)
#pragma unroll
            for (int ni = 0; ni < 8; ni++) mma16816(acc[mi][ni], afr[mi], bfr[ni]);

        if (more) { stA(cur ^ 1); stB(cur ^ 1); }
        __syncthreads();
    }

    // epilogue: add bias, store fp32
    const int er = lane >> 2;
    const int ec = (lane & 3) * 2;
    float bias0[8], bias1[8];
#pragma unroll
    for (int ni = 0; ni < 8; ni++) {
        int col = wn * 64 + ni * 8 + ec;
        bias0[ni] = bih[col] + bhh[col];
        bias1[ni] = bih[col + 1] + bhh[col + 1];
    }
#pragma unroll
    for (int mi = 0; mi < 2; mi++) {
        int row = m0 + wm * 32 + mi * 16 + er;
#pragma unroll
        for (int ni = 0; ni < 8; ni++) {
            int col = wn * 64 + ni * 8 + ec;
            float2 v0 = make_float2(acc[mi][ni][0] + bias0[ni], acc[mi][ni][1] + bias1[ni]);
            float2 v1 = make_float2(acc[mi][ni][2] + bias0[ni], acc[mi][ni][3] + bias1[ni]);
            *(float2*)&g_gx[(size_t)row * Gsz + col]       = v0;
            *(float2*)&g_gx[(size_t)(row + 8) * Gsz + col] = v1;
        }
    }
}

// ============================================================================
// Kernel 2: LSTM recurrence. 1 CTA / batch, 128 threads = 4H gate rows.
// One barrier per step; h exchanged via shfl; also emits bf16 hi/lo h for
// gemm_q's B operand.
// ============================================================================
__global__ __launch_bounds__(128) void lstm_scan(const float* __restrict__ Whh) {
    const int b    = blockIdx.x;
    const int j    = threadIdx.x;
    const int lane = j & 31;
    const int wid  = j >> 5;
    __shared__ __align__(16) float sh_act[2][Gsz];

    float w[Hsz];
#pragma unroll
    for (int k = 0; k < Hsz; k++) w[k] = Whh[j * Hsz + k];

    float c = 0.f, h = 0.f;
    const float* gxb = g_gx + (size_t)b * Tsz * Gsz;
    float gcur  = gxb[j];
    float gnext = gxb[Gsz + j];
    const bool is_g = (wid == 2);

    for (int t = 0; t < Tsz; t++) {
        float gpre = (t + 2 < Tsz) ? gxb[(size_t)(t + 2) * Gsz + j] : 0.f;

        float s0 = gcur, s1 = 0.f, s2 = 0.f, s3 = 0.f;
#pragma unroll
        for (int k = 0; k < Hsz; k += 4) {
            s0 = fmaf(w[k],     __shfl_sync(0xffffffffu, h, k),     s0);
            s1 = fmaf(w[k + 1], __shfl_sync(0xffffffffu, h, k + 1), s1);
            s2 = fmaf(w[k + 2], __shfl_sync(0xffffffffu, h, k + 2), s2);
            s3 = fmaf(w[k + 3], __shfl_sync(0xffffffffu, h, k + 3), s3);
        }
        float z = (s0 + s1) + (s2 + s3);

        float a;
        if (is_g) a = 2.f / (1.f + __expf(-2.f * z)) - 1.f;   // tanh
        else      a = 1.f / (1.f + __expf(-z));               // sigmoid
        sh_act[t & 1][lane * 4 + wid] = a;
        __syncthreads();

        float4 g4 = *(const float4*)&sh_act[t & 1][lane * 4];  // (i,f,g,o)
        c = fmaf(g4.y, c, g4.x * g4.z);
        float tc = 2.f / (1.f + __expf(-2.f * c)) - 1.f;
        h = g4.w * tc;
        if (wid == 0) {
            size_t idx = (size_t)t * NBH + b * Hsz + lane;
            g_hsT[idx] = h;
            __nv_bfloat16 hh = __float2bfloat16(h);
            g_hsT_hi[idx] = hh;
            g_hsT_lo[idx] = __float2bfloat16(h - __bfloat162float(hh));
        }

        gcur = gnext;
        gnext = gpre;
    }
}

// ============================================================================
// Kernel 3: q[s,n] = sum_t Ww[s,t]*hsT[t,n], split-bf16 HMMA, pipelined,
// both operands pre-converted. Fused epilogue:
//   qk[b,s,h] = hsT[s,n]*(q+bw[s]),  fc partial per (batch, m-block).
// M=800(->896), N=4096, K=800. 50 k-iters.
// ============================================================================
#define BPAD 136
#define NIT2 (Tsz / 16)      // 50
__global__ __launch_bounds__(256, 2) void gemm_q_mma(
    const float* __restrict__ bw, const float* __restrict__ Wfc,
    float* __restrict__ qk_out) {
    __shared__ __align__(16) __nv_bfloat16 sAhi[2][128 * APAD], sAlo[2][128 * APAD];
    __shared__ __align__(16) __nv_bfloat16 sBhi[2][16 * BPAD],  sBlo[2][16 * BPAD];
    __shared__ float redfc[512];

    const int m0   = blockIdx.x * 128;
    const int n0   = blockIdx.y * 128;
    const int tid  = threadIdx.x;
    const int lane = tid & 31;
    const int wid  = tid >> 5;
    const int wm   = wid >> 1;
    const int wn   = wid & 1;

    float acc[2][8][4];
#pragma unroll
    for (int mi = 0; mi < 2; mi++)
#pragma unroll
        for (int ni = 0; ni < 8; ni++)
#pragma unroll
            for (int e = 0; e < 4; e++) acc[mi][ni][e] = 0.f;

    const int alr = tid >> 1;        // A row (m)
    const int alk = (tid & 1) * 8;
    const int blr = tid >> 4;        // B row (k)
    const int bln = (tid & 15) * 8;
    const bool arow_ok = (m0 + alr < Tsz);

    const int amrow = lane & 15;
    const int akcol = (lane >> 4) * 8;
    int offA[2];
#pragma unroll
    for (int mi = 0; mi < 2; mi++)
        offA[mi] = (wm * 32 + mi * 16 + amrow) * APAD + akcol;
    const int qbrow = lane & 15;
    const int qbcol = (lane >> 4) * 8;
    int offB[4];
#pragma unroll
    for (int nb = 0; nb < 4; nb++)
        offB[nb] = qbrow * BPAD + wn * 64 + nb * 16 + qbcol;

    uint4 pah, pal, pbh, pbl;
    auto loadA = [&](int k0) {
        if (arow_ok) {
            pah = *(const uint4*)&g_Ww_hi[(size_t)(m0 + alr) * Tsz + k0 + alk];
            pal = *(const uint4*)&g_Ww_lo[(size_t)(m0 + alr) * Tsz + k0 + alk];
        } else {
            pah = make_uint4(0, 0, 0, 0);
            pal = make_uint4(0, 0, 0, 0);
        }
    };
    auto loadB = [&](int k0) {
        pbh = *(const uint4*)&g_hsT_hi[(size_t)(k0 + blr) * NBH + n0 + bln];
        pbl = *(const uint4*)&g_hsT_lo[(size_t)(k0 + blr) * NBH + n0 + bln];
    };
    auto stA = [&](int buf) {
        *(uint4*)&sAhi[buf][alr * APAD + alk] = pah;
        *(uint4*)&sAlo[buf][alr * APAD + alk] = pal;
    };
    auto stB = [&](int buf) {
        *(uint4*)&sBhi[buf][blr * BPAD + bln] = pbh;
        *(uint4*)&sBlo[buf][blr * BPAD + bln] = pbl;
    };

    loadA(0); loadB(0);
    stA(0); stB(0);
    __syncthreads();

#pragma unroll 1
    for (int it = 0; it < NIT2; it++) {
        const int cur = it & 1;
        const bool more = (it + 1 < NIT2);
        if (more) { loadA((it + 1) * 16); loadB((it + 1) * 16); }

        uint32_t afr[2][4], alo2[2][4], bfr[8][2];
        ldsm4(afr[0], sptr(&sAhi[cur][offA[0]]));
        ldsm4(afr[1], sptr(&sAhi[cur][offA[1]]));
#pragma unroll
        for (int nb = 0; nb < 4; nb++) {
            uint32_t r[4];
            ldsm4t(r, sptr(&sBhi[cur][offB[nb]]));
            bfr[2 * nb][0] = r[0]; bfr[2 * nb][1] = r[1];
            bfr[2 * nb + 1][0] = r[2]; bfr[2 * nb + 1][1] = r[3];
        }
#pragma unroll
        for (int mi = 0; mi < 2; mi++)
#pragma unroll
            for (int ni = 0; ni < 8; ni++) mma16816(acc[mi][ni], afr[mi], bfr[ni]);

        ldsm4(alo2[0], sptr(&sAlo[cur][offA[0]]));
        ldsm4(alo2[1], sptr(&sAlo[cur][offA[1]]));
#pragma unroll
        for (int mi = 0; mi < 2; mi++)
#pragma unroll
            for (int ni = 0; ni < 8; ni++) mma16816(acc[mi][ni], alo2[mi], bfr[ni]);

#pragma unroll
        for (int nb = 0; nb < 4; nb++) {
            uint32_t r[4];
            ldsm4t(r, sptr(&sBlo[cur][offB[nb]]));
            bfr[2 * nb][0] = r[0]; bfr[2 * nb][1] = r[1];
            bfr[2 * nb + 1][0] = r[2]; bfr[2 * nb + 1][1] = r[3];
        }
#pragma unroll
        for (int mi = 0; mi < 2; mi++)
#pragma unroll
            for (int ni = 0; ni < 8; ni++) mma16816(acc[mi][ni], afr[mi], bfr[ni]);

        if (more) { stA(cur ^ 1); stB(cur ^ 1); }
        __syncthreads();
    }

    // ---- fused epilogue: qk = hsT*(q+bw), fc partials ----
    const int er = lane >> 2;
    const int ec = (lane & 3) * 2;
    float pb[2] = {0.f, 0.f};      // local batch = wn*2 + (ni>>2)
#pragma unroll
    for (int mi = 0; mi < 2; mi++) {
        int r0 = m0 + wm * 32 + mi * 16 + er;
        int r1 = r0 + 8;
        float bw0 = (r0 < Tsz) ? bw[r0] : 0.f;
        float bw1 = (r1 < Tsz) ? bw[r1] : 0.f;
#pragma unroll
        for (int ni = 0; ni < 8; ni++) {
            int n  = n0 + wn * 64 + ni * 8 + ec;
            int bb = n >> 5, hh = n & 31;
            int bi = ni >> 2;
            if (r0 < Tsz) {
                float2 o = *(const float2*)&g_hsT[(size_t)r0 * NBH + n];
                float2 wf = *(const float2*)&Wfc[r0 * Hsz + hh];
                float2 v = make_float2(o.x * (acc[mi][ni][0] + bw0),
                                       o.y * (acc[mi][ni][1] + bw0));
                *(float2*)&qk_out[(size_t)bb * (Tsz * Hsz) + r0 * Hsz + hh] = v;
                pb[bi] = fmaf(v.x, wf.x, fmaf(v.y, wf.y, pb[bi]));
            }
            if (r1 < Tsz) {
                float2 o = *(const float2*)&g_hsT[(size_t)r1 * NBH + n];
                float2 wf = *(const float2*)&Wfc[r1 * Hsz + hh];
                float2 v = make_float2(o.x * (acc[mi][ni][2] + bw1),
                                       o.y * (acc[mi][ni][3] + bw1));
                *(float2*)&qk_out[(size_t)bb * (Tsz * Hsz) + r1 * Hsz + hh] = v;
                pb[bi] = fmaf(v.x, wf.x, fmaf(v.y, wf.y, pb[bi]));
            }
        }
    }
    // deterministic CTA reduction: 4 local batches x 128 contributors
    redfc[(wn * 2 + 0) * 128 + wm * 32 + lane] = pb[0];
    redfc[(wn * 2 + 1) * 128 + wm * 32 + lane] = pb[1];
    __syncthreads();
    if (wid < 4) {   // warp wid handles local batch wid
        float s = redfc[wid * 128 + lane] + redfc[wid * 128 + lane + 32]
                + redfc[wid * 128 + lane + 64] + redfc[wid * 128 + lane + 96];
#pragma unroll
        for (int o = 16; o > 0; o >>= 1) s += __shfl_xor_sync(0xffffffffu, s, o);
        if (lane == 0) g_fcpart[((n0 >> 5) + wid) * NMB + blockIdx.x] = s;
    }
}

// Final fc: out[b] = bfc + sum over 7 m-block partials
__global__ void fc_final(const float* __restrict__ bfc, float* __restrict__ fc_out) {
    int b = threadIdx.x;
    float s = bfc[0];
#pragma unroll
    for (int i = 0; i < NMB; i++) s += g_fcpart[b * NMB + i];
    fc_out[b] = s;
}

// ============================================================================
// Launcher
// ============================================================================
extern "C" void kernel_launch(void* const* d_in, const int* in_sizes, int n_in,
                              void* d_out, int out_size) {
    const float* x   = (const float*)d_in[0];
    const float* Wih = (const float*)d_in[1];
    const float* Whh = (const float*)d_in[2];
    const float* bih = (const float*)d_in[3];
    const float* bhh = (const float*)d_in[4];
    const float* Ww  = (const float*)d_in[5];
    const float* bw  = (const float*)d_in[6];
    const float* Wfc = (const float*)d_in[7];
    const float* bfc = (const float*)d_in[8];
    float* out = (float*)d_out;

    const long QK = (long)Bsz * Tsz * Hsz;
    float* fc_out;
    float* qk_out;
    if (out_size == (int)(QK + Bsz)) {       // tuple (out_fc, qk) concatenated
        fc_out = out;
        qk_out = out + Bsz;
    } else if (out_size == (int)QK) {        // qk only
        qk_out = out;
        cudaGetSymbolAddress((void**)&fc_out, g_fc_scratch);
    } else {                                 // fc only
        fc_out = out;
        cudaGetSymbolAddress((void**)&qk_out, g_qk_scratch);
    }

    // 0. one-time operand splits
    cvt_wih<<<(128 * IszP + 255) / 256, 256>>>(Wih);
    cvt_ww<<<(800 * 800 + 255) / 256, 256>>>(Ww);

    // 1. input projection GEMM (pipelined split-bf16)
    gemm_gx_mma<<<(Bsz * Tsz) / 128, 256>>>(x, bih, bhh);

    // 2. sequential LSTM scan
    lstm_scan<<<Bsz, 128>>>(Whh);

    // 3. attention GEMM + fused qk/fc epilogue
    dim3 g2(NMB, NBH / 128);                 // (7, 32)
    gemm_q_mma<<<g2, 256>>>(bw, Wfc, qk_out);

    // 4. final fc reduction
    fc_final<<<1, Bsz>>>(bfc, fc_out);
}